// round 16
// baseline (speedup 1.0000x reference)
#include <cuda_runtime.h>
#include <math_constants.h>

// ============================================================================
// Chamfer loss: ONE persistent kernel, exact uniform-grid NN with CSR layout.
// Base = R13 (41.5us-class). R16 delta (only): SCRAMBLED query order in P5.
// CSR-sorted task order put all sparse-region (escaping) queries into the
// same few warps -> divergent 8-group escape unions = straggler tail. The
// bijection q -> (q*24593) & (total-1) (odd multiplier, total = 2^k) spreads
// escapes uniformly across warps; identity fallback for non-pow2 totals.
// Phases: P1 bin | P2 chunk scan (+self-zero) | P3 offsets | P4 fill | P5 query
// Exact: 3x3 margin gb = per-axis min(cs+frac, 2cs-frac); escape rows at |dy|
// have gap >= (dy-1)*cs; width W exact when (W*cs)^2 >= best, else widen.
// Fixed bounds [-6.5,6.5]: clamped points are farther than their cell implies.
// ============================================================================

#define G      128
#define NCELL  (G * G)
#define TC     (2 * NCELL)
#define TMAX   65536
#define TPB    512
#define NW     (TPB / 32)
#define MAXBLK 256
#define FULL   0xFFFFFFFFu

#define X0F  (-6.5f)
#define Y0F  (-6.5f)
#define CSF  (0.1015625f)              // 13/128, exact in binary
#define INVF (9.846153846153847f)      // 128/13

__device__ int          g_arr;
__device__ volatile int g_gen;
__device__ int          g_task;
__device__ int          g_blksum[MAXBLK];
__device__ int          g_cnt[TC];     // zero at load; self-cleaned each run
__device__ int          g_off[TC + 1];
__device__ int          g_cid[TMAX];   // fallback path only
__device__ int          g_rank[TMAX];  // fallback path only
__device__ float2       g_pts[TMAX];

static __device__ __forceinline__ void gridbar(int nblk) {
    __syncthreads();
    if (threadIdx.x == 0) {
        __threadfence();
        int g = g_gen;
        if (atomicAdd(&g_arr, 1) == nblk - 1) {
            g_arr = 0;
            __threadfence();
            g_gen = g + 1;
        } else {
            while (g_gen == g) { }
        }
    }
    __syncthreads();
}

// Block-wide exclusive scan; warp-uniform shfls, full masks.
static __device__ __forceinline__ int block_excl_scan(int v, int tid,
                                                      int* s_warp, int* total) {
    int lane = tid & 31, w = tid >> 5;
    int x = v;
#pragma unroll
    for (int o = 1; o < 32; o <<= 1) {
        int y = __shfl_up_sync(FULL, x, o);
        if (lane >= o) x += y;
    }
    if (lane == 31) s_warp[w] = x;
    __syncthreads();
    if (w == 0) {
        int y = (lane < NW) ? s_warp[lane] : 0;
#pragma unroll
        for (int o = 1; o < NW; o <<= 1) {
            int z = __shfl_up_sync(FULL, y, o);
            if (lane >= o) y += z;
        }
        if (lane < NW) s_warp[lane] = y;
    }
    __syncthreads();
    int base = w ? s_warp[w - 1] : 0;
    *total = s_warp[NW - 1];
    __syncthreads();
    return base + x - v;
}

static __device__ __forceinline__ int cell_clamp(float v, float o) {
    return min(G - 1, max(0, (int)((v - o) * INVF)));
}

// ---------------------------------------------------------------------------
__global__ __launch_bounds__(TPB) void chamfer_fused(
    const float* __restrict__ A, int na,
    const float* __restrict__ B, int nb,
    float* __restrict__ out, int nblk)
{
    const int tid  = threadIdx.x;
    const int b    = blockIdx.x;
    const int gsz  = nblk * TPB;
    const int gtid = b * TPB + tid;
    const int total = na + nb;

    __shared__ int s_warp[NW];
    __shared__ int s_base;

    // ---------------- P1: bin (g_cnt zero from load / previous self-clean) ----
    if (gtid == 0) { out[0] = 0.0f; g_task = 0; g_off[TC] = total; }

    // Register-carried point: each thread owns <= 1 point at this size.
    float2 myp = make_float2(0.0f, 0.0f);
    int myc = -1, myrank = 0;
    if (gtid < total) {
        myp = (gtid < na) ? ((const float2*)A)[gtid]
                          : ((const float2*)B)[gtid - na];
        int s = (gtid < na) ? 0 : 1;
        myc = s * NCELL + cell_clamp(myp.y, Y0F) * G + cell_clamp(myp.x, X0F);
        myrank = atomicAdd(&g_cnt[myc], 1);
    }
    // Fallback (total > gsz): memory-carried, not hit at this problem size.
    for (int i = gtid + gsz; i < total; i += gsz) {
        const float2 p = (i < na) ? ((const float2*)A)[i]
                                  : ((const float2*)B)[i - na];
        int s = (i < na) ? 0 : 1;
        int c = s * NCELL + cell_clamp(p.y, Y0F) * G + cell_clamp(p.x, X0F);
        g_cid[i]  = c;
        g_rank[i] = atomicAdd(&g_cnt[c], 1);
    }
    gridbar(nblk);

    // ---------------- P2: per-block chunk scan + self-zero ----------------
    const int cpb = (TC + nblk - 1) / nblk;   // 216 @ nblk=152, <= TPB
    const int idx = b * cpb + tid;
    const bool own = (tid < cpb && idx < TC);
    int v = own ? g_cnt[idx] : 0;
    if (own) g_cnt[idx] = 0;                  // clean for next launch
    int btot;
    int excl = block_excl_scan(v, tid, s_warp, &btot);
    if (tid == 0) g_blksum[b] = btot;
    gridbar(nblk);

    // ---------------- P3: block bases -> CSR offsets ----------------
    {
        int bv = (tid < nblk) ? g_blksum[tid] : 0;
        int t2;
        int e2 = block_excl_scan(bv, tid, s_warp, &t2);
        if (tid == b) s_base = e2;
        __syncthreads();
        if (own) g_off[idx] = s_base + excl;
    }
    gridbar(nblk);

    // ---------------- P4: scatter fill (register-carried fast path) ----------
    if (myc >= 0) g_pts[g_off[myc] + myrank] = myp;
    for (int i = gtid + gsz; i < total; i += gsz) {
        const float2 p = (i < na) ? ((const float2*)A)[i]
                                  : ((const float2*)B)[i - na];
        g_pts[g_off[g_cid[i]] + g_rank[i]] = p;
    }
    gridbar(nblk);

    // ---------------- P5: query (4 lanes/query; scrambled dynamic chunks) ----
    float acc = 0.0f;
    const int ntask = 4 * total;              // multiple of 4
    const int lane  = tid & 31;
    const unsigned gmask = 0xFu << (lane & 28);
    const float INF = CUDART_INF_F;
    // Scramble is a bijection only for power-of-two totals.
    const bool pow2 = (total & (total - 1)) == 0;
    const int qmask = total - 1;

    for (;;) {
        int chunk;
        if (lane == 0) chunk = atomicAdd(&g_task, 32);
        chunk = __shfl_sync(FULL, chunk, 0);
        if (chunk >= ntask) break;

        int task = chunk + lane;
        bool valid = task < ntask;
        if (!valid) task = ntask - 1;         // clamped lanes: complete group, discarded
        int q   = task >> 2;                  // same for all 4 lanes of a group
        int sub = task & 3;
        if (pow2) q = (q * 24593) & qmask;    // spread escapes across warps
        float2 Q = g_pts[q];
        int cx = cell_clamp(Q.x, X0F);
        int cy = cell_clamp(Q.y, Y0F);
        const int* __restrict__ off = g_off + ((q < na) ? NCELL : 0);

        float best = INF;

        // fast path: 3x3; all 6 row-offsets prefetched (independent loads).
        {
            int xlo = max(cx - 1, 0), xhi = min(cx + 1, G - 1);
            int sg[3], eg[3];
#pragma unroll
            for (int j = 0; j < 3; j++) {
                int yy = min(max(cy - 1 + j, 0), G - 1);
                sg[j] = off[yy * G + xlo];
                eg[j] = off[yy * G + xhi + 1];
            }
#pragma unroll
            for (int j = 0; j < 3; j++)
                for (int k = sg[j] + sub; k < eg[j]; k += 4) {
                    float2 p = g_pts[k];
                    float dx = Q.x - p.x, dy = Q.y - p.y;
                    best = fminf(best, fmaf(dx, dx, dy * dy));
                }
        }
        best = fminf(best, __shfl_xor_sync(gmask, best, 1));
        best = fminf(best, __shfl_xor_sync(gmask, best, 2));

        // exact exit bound from true position in cell (conservative for any f)
        float fx = (Q.x - X0F) - (float)cx * CSF;
        float fy = (Q.y - Y0F) - (float)cy * CSF;
        float gb = fminf(fminf(CSF + fx, 2.0f * CSF - fx),
                         fminf(CSF + fy, 2.0f * CSF - fy));
        gb = fmaxf(gb, 0.0f);

        // escape: row-band scan (group-uniform control flow)
        if (!(best <= gb * gb)) {
            int W = 12;
            for (;;) {
                if (best < INF) {
                    int Wn = (int)(sqrtf(best) * INVF) + 2;
                    if (Wn > W) W = Wn;
                }
                if (W > G - 1) W = G - 1;
                int xlo = max(cx - W, 0), xhi = min(cx + W, G - 1);

                for (int dy = 0; dy < G; dy++) {
                    if (dy >= 1 && best < INF) {
                        float bb = (float)(dy - 1) * CSF;
                        if (bb * bb >= best) break;
                    }
                    int yt = cy - dy, yb = cy + dy;
                    if (yt < 0 && yb > G - 1) break;
                    if (yt >= 0) {
                        int s0 = off[yt * G + xlo], e0 = off[yt * G + xhi + 1];
                        for (int k = s0 + sub; k < e0; k += 4) {
                            float2 p = g_pts[k];
                            float dx = Q.x - p.x, dyv = Q.y - p.y;
                            best = fminf(best, fmaf(dx, dx, dyv * dyv));
                        }
                    }
                    if (dy > 0 && yb <= G - 1) {
                        int s0 = off[yb * G + xlo], e0 = off[yb * G + xhi + 1];
                        for (int k = s0 + sub; k < e0; k += 4) {
                            float2 p = g_pts[k];
                            float dx = Q.x - p.x, dyv = Q.y - p.y;
                            best = fminf(best, fmaf(dx, dx, dyv * dyv));
                        }
                    }
                    best = fminf(best, __shfl_xor_sync(gmask, best, 1));
                    best = fminf(best, __shfl_xor_sync(gmask, best, 2));
                }

                bool fullwidth = (xlo == 0 && xhi == G - 1);
                if (best < INF) {
                    float wb = (float)W * CSF;
                    if (wb * wb >= best || fullwidth) break;
                } else if (fullwidth) {
                    break;
                }
                W <<= 1;
            }
        }

        if (sub == 0 && valid) acc += sqrtf(best);
    }

    // Block sum -> one atomicAdd per block.
#pragma unroll
    for (int o = 16; o > 0; o >>= 1)
        acc += __shfl_down_sync(FULL, acc, o);
    {
        __shared__ float ws[NW];
        int w = tid >> 5;
        if (lane == 0) ws[w] = acc;
        __syncthreads();
        if (w == 0) {
            acc = (lane < NW) ? ws[lane] : 0.0f;
#pragma unroll
            for (int o = 16; o > 0; o >>= 1)
                acc += __shfl_down_sync(FULL, acc, o);
            if (lane == 0) atomicAdd(out, acc);
        }
    }
}

// ---------------------------------------------------------------------------
extern "C" void kernel_launch(void* const* d_in, const int* in_sizes, int n_in,
                              void* d_out, int out_size) {
    const float* A = (const float*)d_in[0];
    const float* B = (const float*)d_in[1];
    int na = in_sizes[0] / 2;
    int nb = in_sizes[1] / 2;
    float* out = (float*)d_out;

    int sms = 0;
    if (cudaDeviceGetAttribute(&sms, cudaDevAttrMultiProcessorCount, 0) != cudaSuccess
        || sms <= 0) sms = 148;
    int nblk = sms;
    if (nblk > MAXBLK) nblk = MAXBLK;
    if (nblk < 64)     nblk = 64;      // keep cpb <= TPB for the chunk scan

    chamfer_fused<<<nblk, TPB>>>(A, na, B, nb, out, nblk);
}

// round 17
// speedup vs baseline: 1.2202x; 1.2202x over previous
#include <cuda_runtime.h>
#include <math_constants.h>

// ============================================================================
// Chamfer loss: ONE persistent kernel, exact uniform-grid NN with CSR layout.
// Base = R13 (41.5us best). R17 delta (only): the CSR offset table (131 KB)
// is copied into dynamic SHARED MEMORY per block after P3; all P4/P5 offset
// reads become LDS (29 cyc) instead of L2 (~234 cyc), shortening the per-task
// dependent chain Q -> offsets -> candidates and the escape row-walk loop.
// Phases: P1 bin | P2 chunk scan (+self-zero) | P3 offsets | copy | P4 | P5
// Exact: 3x3 margin gb = per-axis min(cs+frac, 2cs-frac); escape rows at |dy|
// have gap >= (dy-1)*cs; width W exact when (W*cs)^2 >= best, else widen.
// Fixed bounds [-6.5,6.5]: clamped points are farther than their cell implies.
// ============================================================================

#define G      128
#define NCELL  (G * G)
#define TC     (2 * NCELL)
#define TMAX   65536
#define TPB    512
#define NW     (TPB / 32)
#define MAXBLK 256
#define FULL   0xFFFFFFFFu
#define SMEM_OFF_BYTES ((TC + 1) * (int)sizeof(int))

#define X0F  (-6.5f)
#define Y0F  (-6.5f)
#define CSF  (0.1015625f)              // 13/128, exact in binary
#define INVF (9.846153846153847f)      // 128/13

__device__ int          g_arr;
__device__ volatile int g_gen;
__device__ int          g_task;
__device__ int          g_blksum[MAXBLK];
__device__ int          g_cnt[TC];     // zero at load; self-cleaned each run
__device__ int          g_off[TC + 1];
__device__ int          g_cid[TMAX];   // fallback path only
__device__ int          g_rank[TMAX];  // fallback path only
__device__ float2       g_pts[TMAX];

static __device__ __forceinline__ void gridbar(int nblk) {
    __syncthreads();
    if (threadIdx.x == 0) {
        __threadfence();
        int g = g_gen;
        if (atomicAdd(&g_arr, 1) == nblk - 1) {
            g_arr = 0;
            __threadfence();
            g_gen = g + 1;
        } else {
            while (g_gen == g) { }
        }
    }
    __syncthreads();
}

// Block-wide exclusive scan; warp-uniform shfls, full masks.
static __device__ __forceinline__ int block_excl_scan(int v, int tid,
                                                      int* s_warp, int* total) {
    int lane = tid & 31, w = tid >> 5;
    int x = v;
#pragma unroll
    for (int o = 1; o < 32; o <<= 1) {
        int y = __shfl_up_sync(FULL, x, o);
        if (lane >= o) x += y;
    }
    if (lane == 31) s_warp[w] = x;
    __syncthreads();
    if (w == 0) {
        int y = (lane < NW) ? s_warp[lane] : 0;
#pragma unroll
        for (int o = 1; o < NW; o <<= 1) {
            int z = __shfl_up_sync(FULL, y, o);
            if (lane >= o) y += z;
        }
        if (lane < NW) s_warp[lane] = y;
    }
    __syncthreads();
    int base = w ? s_warp[w - 1] : 0;
    *total = s_warp[NW - 1];
    __syncthreads();
    return base + x - v;
}

static __device__ __forceinline__ int cell_clamp(float v, float o) {
    return min(G - 1, max(0, (int)((v - o) * INVF)));
}

// ---------------------------------------------------------------------------
__global__ __launch_bounds__(TPB) void chamfer_fused(
    const float* __restrict__ A, int na,
    const float* __restrict__ B, int nb,
    float* __restrict__ out, int nblk)
{
    extern __shared__ int s_off[];     // (TC+1) ints = 131 KB
    const int tid  = threadIdx.x;
    const int b    = blockIdx.x;
    const int gsz  = nblk * TPB;
    const int gtid = b * TPB + tid;
    const int total = na + nb;

    __shared__ int s_warp[NW];
    __shared__ int s_base;

    // ---------------- P1: bin (g_cnt zero from load / previous self-clean) ----
    if (gtid == 0) { out[0] = 0.0f; g_task = 0; g_off[TC] = total; }

    // Register-carried point: each thread owns <= 1 point at this size.
    float2 myp = make_float2(0.0f, 0.0f);
    int myc = -1, myrank = 0;
    if (gtid < total) {
        myp = (gtid < na) ? ((const float2*)A)[gtid]
                          : ((const float2*)B)[gtid - na];
        int s = (gtid < na) ? 0 : 1;
        myc = s * NCELL + cell_clamp(myp.y, Y0F) * G + cell_clamp(myp.x, X0F);
        myrank = atomicAdd(&g_cnt[myc], 1);
    }
    // Fallback (total > gsz): memory-carried, not hit at this problem size.
    for (int i = gtid + gsz; i < total; i += gsz) {
        const float2 p = (i < na) ? ((const float2*)A)[i]
                                  : ((const float2*)B)[i - na];
        int s = (i < na) ? 0 : 1;
        int c = s * NCELL + cell_clamp(p.y, Y0F) * G + cell_clamp(p.x, X0F);
        g_cid[i]  = c;
        g_rank[i] = atomicAdd(&g_cnt[c], 1);
    }
    gridbar(nblk);

    // ---------------- P2: per-block chunk scan + self-zero ----------------
    const int cpb = (TC + nblk - 1) / nblk;   // 216 @ nblk=152, <= TPB
    const int idx = b * cpb + tid;
    const bool own = (tid < cpb && idx < TC);
    int v = own ? g_cnt[idx] : 0;
    if (own) g_cnt[idx] = 0;                  // clean for next launch
    int btot;
    int excl = block_excl_scan(v, tid, s_warp, &btot);
    if (tid == 0) g_blksum[b] = btot;
    gridbar(nblk);

    // ---------------- P3: block bases -> CSR offsets ----------------
    {
        int bv = (tid < nblk) ? g_blksum[tid] : 0;
        int t2;
        int e2 = block_excl_scan(bv, tid, s_warp, &t2);
        if (tid == b) s_base = e2;
        __syncthreads();
        if (own) g_off[idx] = s_base + excl;
    }
    gridbar(nblk);

    // ---------------- copy offset table into shared memory -------------------
    {
        const int4* src = (const int4*)g_off;
        int4* dst = (int4*)s_off;
        for (int i = tid; i < TC / 4; i += TPB) dst[i] = src[i];   // TC%4==0
        if (tid == 0) s_off[TC] = g_off[TC];
    }
    __syncthreads();

    // ---------------- P4: scatter fill (register-carried fast path) ----------
    if (myc >= 0) g_pts[s_off[myc] + myrank] = myp;
    for (int i = gtid + gsz; i < total; i += gsz) {
        const float2 p = (i < na) ? ((const float2*)A)[i]
                                  : ((const float2*)B)[i - na];
        g_pts[s_off[g_cid[i]] + g_rank[i]] = p;
    }
    gridbar(nblk);

    // ---------------- P5: query (4 lanes/query; dynamic warp chunks) ---------
    float acc = 0.0f;
    const int ntask = 4 * total;              // multiple of 4
    const int lane  = tid & 31;
    const unsigned gmask = 0xFu << (lane & 28);
    const float INF = CUDART_INF_F;

    for (;;) {
        int chunk;
        if (lane == 0) chunk = atomicAdd(&g_task, 32);
        chunk = __shfl_sync(FULL, chunk, 0);
        if (chunk >= ntask) break;

        int task = chunk + lane;
        bool valid = task < ntask;
        if (!valid) task = ntask - 1;         // clamped lanes: complete group, discarded
        int q   = task >> 2;
        int sub = task & 3;
        float2 Q = g_pts[q];
        int cx = cell_clamp(Q.x, X0F);
        int cy = cell_clamp(Q.y, Y0F);
        const int* off = s_off + ((q < na) ? NCELL : 0);   // SMEM offsets

        float best = INF;

        // fast path: 3x3; all 6 row-offsets prefetched (now LDS, 29 cyc).
        {
            int xlo = max(cx - 1, 0), xhi = min(cx + 1, G - 1);
            int sg[3], eg[3];
#pragma unroll
            for (int j = 0; j < 3; j++) {
                int yy = min(max(cy - 1 + j, 0), G - 1);
                sg[j] = off[yy * G + xlo];
                eg[j] = off[yy * G + xhi + 1];
            }
#pragma unroll
            for (int j = 0; j < 3; j++)
                for (int k = sg[j] + sub; k < eg[j]; k += 4) {
                    float2 p = g_pts[k];
                    float dx = Q.x - p.x, dy = Q.y - p.y;
                    best = fminf(best, fmaf(dx, dx, dy * dy));
                }
        }
        best = fminf(best, __shfl_xor_sync(gmask, best, 1));
        best = fminf(best, __shfl_xor_sync(gmask, best, 2));

        // exact exit bound from true position in cell (conservative for any f)
        float fx = (Q.x - X0F) - (float)cx * CSF;
        float fy = (Q.y - Y0F) - (float)cy * CSF;
        float gb = fminf(fminf(CSF + fx, 2.0f * CSF - fx),
                         fminf(CSF + fy, 2.0f * CSF - fy));
        gb = fmaxf(gb, 0.0f);

        // escape: row-band scan (group-uniform control flow; offsets in smem)
        if (!(best <= gb * gb)) {
            int W = 12;
            for (;;) {
                if (best < INF) {
                    int Wn = (int)(sqrtf(best) * INVF) + 2;
                    if (Wn > W) W = Wn;
                }
                if (W > G - 1) W = G - 1;
                int xlo = max(cx - W, 0), xhi = min(cx + W, G - 1);

                for (int dy = 0; dy < G; dy++) {
                    if (dy >= 1 && best < INF) {
                        float bb = (float)(dy - 1) * CSF;
                        if (bb * bb >= best) break;
                    }
                    int yt = cy - dy, yb = cy + dy;
                    if (yt < 0 && yb > G - 1) break;
                    if (yt >= 0) {
                        int s0 = off[yt * G + xlo], e0 = off[yt * G + xhi + 1];
                        for (int k = s0 + sub; k < e0; k += 4) {
                            float2 p = g_pts[k];
                            float dx = Q.x - p.x, dyv = Q.y - p.y;
                            best = fminf(best, fmaf(dx, dx, dyv * dyv));
                        }
                    }
                    if (dy > 0 && yb <= G - 1) {
                        int s0 = off[yb * G + xlo], e0 = off[yb * G + xhi + 1];
                        for (int k = s0 + sub; k < e0; k += 4) {
                            float2 p = g_pts[k];
                            float dx = Q.x - p.x, dyv = Q.y - p.y;
                            best = fminf(best, fmaf(dx, dx, dyv * dyv));
                        }
                    }
                    best = fminf(best, __shfl_xor_sync(gmask, best, 1));
                    best = fminf(best, __shfl_xor_sync(gmask, best, 2));
                }

                bool fullwidth = (xlo == 0 && xhi == G - 1);
                if (best < INF) {
                    float wb = (float)W * CSF;
                    if (wb * wb >= best || fullwidth) break;
                } else if (fullwidth) {
                    break;
                }
                W <<= 1;
            }
        }

        if (sub == 0 && valid) acc += sqrtf(best);
    }

    // Block sum -> one atomicAdd per block.
#pragma unroll
    for (int o = 16; o > 0; o >>= 1)
        acc += __shfl_down_sync(FULL, acc, o);
    {
        __shared__ float ws[NW];
        int w = tid >> 5;
        if (lane == 0) ws[w] = acc;
        __syncthreads();
        if (w == 0) {
            acc = (lane < NW) ? ws[lane] : 0.0f;
#pragma unroll
            for (int o = 16; o > 0; o >>= 1)
                acc += __shfl_down_sync(FULL, acc, o);
            if (lane == 0) atomicAdd(out, acc);
        }
    }
}

// ---------------------------------------------------------------------------
extern "C" void kernel_launch(void* const* d_in, const int* in_sizes, int n_in,
                              void* d_out, int out_size) {
    const float* A = (const float*)d_in[0];
    const float* B = (const float*)d_in[1];
    int na = in_sizes[0] / 2;
    int nb = in_sizes[1] / 2;
    float* out = (float*)d_out;

    int sms = 0;
    if (cudaDeviceGetAttribute(&sms, cudaDevAttrMultiProcessorCount, 0) != cudaSuccess
        || sms <= 0) sms = 148;
    int nblk = sms;
    if (nblk > MAXBLK) nblk = MAXBLK;
    if (nblk < 64)     nblk = 64;      // keep cpb <= TPB for the chunk scan

    cudaFuncSetAttribute(chamfer_fused,
                         cudaFuncAttributeMaxDynamicSharedMemorySize,
                         SMEM_OFF_BYTES);
    chamfer_fused<<<nblk, TPB, SMEM_OFF_BYTES>>>(A, na, B, nb, out, nblk);
}